// round 12
// baseline (speedup 1.0000x reference)
#include <cuda_runtime.h>
#include <cuda_bf16.h>
#include <cstdint>

#define H 2048
#define E 64
#define MAXN 16384
#define TILE_M 128
#define SUPERK 128
#define NSUPER (H / SUPERK)  // 16
#define MAXFLAG 512

// ---------------- device scratch ----------------
__device__ __align__(16) __nv_bfloat16 g_Wh[E * H];
__device__ __align__(16) __nv_bfloat16 g_Wl[E * H];
__device__ float g_partial[(MAXN / TILE_M) * E];
__device__ int   g_cnt[E];
__device__ int   g_nflag;
__device__ int   g_flaglist[MAXFLAG];

// ---------------- helpers ----------------
__device__ __forceinline__ uint32_t smem_u32(const void* p) {
    uint32_t a;
    asm("{ .reg .u64 t; cvta.to.shared.u64 t, %1; cvt.u32.u64 %0, t; }" : "=r"(a) : "l"(p));
    return a;
}
__device__ __forceinline__ uint32_t sw128(uint32_t o) { return o ^ ((o >> 3) & 0x70); }

__device__ __forceinline__ void split2(float v, float& h, float& l) {
    h = __bfloat162float(__float2bfloat16_rn(v));
    l = v - h;
}
__device__ __forceinline__ uint32_t packbf(float a, float b) {
    __nv_bfloat162 t = __floats2bfloat162_rn(a, b);
    return *reinterpret_cast<uint32_t*>(&t);
}

#define CP_ASYNC16(dst, src)                                                             \
    asm volatile("cp.async.cg.shared.global [%0], [%1], 16;" :: "r"(dst), "l"(src))
#define CP_COMMIT()  asm volatile("cp.async.commit_group;" ::: "memory")
#define CP_WAIT0()   asm volatile("cp.async.wait_group 0;" ::: "memory")

#define LDSM4(r, addr)                                                                   \
    asm volatile("ldmatrix.sync.aligned.m8n8.x4.shared.b16 {%0,%1,%2,%3}, [%4];"         \
        : "=r"((r)[0]), "=r"((r)[1]), "=r"((r)[2]), "=r"((r)[3]) : "r"(addr))

#define MMA16816(ac, a, b0, b1)                                                          \
    asm volatile("mma.sync.aligned.m16n8k16.row.col.f32.bf16.bf16.f32 "                  \
        "{%0,%1,%2,%3}, {%4,%5,%6,%7}, {%8,%9}, {%0,%1,%2,%3};"                          \
        : "+f"((ac)[0]), "+f"((ac)[1]), "+f"((ac)[2]), "+f"((ac)[3])                     \
        : "r"((a)[0]), "r"((a)[1]), "r"((a)[2]), "r"((a)[3]), "r"(b0), "r"(b1))

// ---------------- kernel 0: split W once, zero counters ----------------
__global__ __launch_bounds__(256) void prep_kernel(const float* __restrict__ W) {
    int i = blockIdx.x * 256 + threadIdx.x;
    if (i < E * H) {
        float v = W[i], h, l;
        split2(v, h, l);
        g_Wh[i] = __float2bfloat16_rn(h);
        g_Wl[i] = __float2bfloat16_rn(l);
    }
    if (blockIdx.x == 0 && threadIdx.x < E) g_cnt[threadIdx.x] = 0;
    if (blockIdx.x == 0 && threadIdx.x == 0) g_nflag = 0;
}

// ---------------- kernel 1: fused 3-term split-bf16 HMMA GEMM + softmax/top2 ----------------
// Per sub-tile (K=64): A_hi@0 A_lo@16K B_hi@32K B_lo@40K  (48KB)
// Super-chunk buffer = 2 sub-tiles = 96KB; double-buffered = 192KB.
static constexpr int A_SZ   = 16384;
static constexpr int B_SZ   = 8192;
static constexpr int B_OFFS = 2 * A_SZ;            // 32768
static constexpr int SUB_SZ = B_OFFS + 2 * B_SZ;   // 49152
static constexpr int BUF_SZ = 2 * SUB_SZ;          // 98304
static constexpr int OFF_SP = 2 * BUF_SZ;          // 196608
static constexpr int SMEM_TOTAL = OFF_SP + 4 * E * 4;  // 197632

__global__ __launch_bounds__(256, 1) void gemm_kernel(const float* __restrict__ x,
                                                      float* __restrict__ out, int N) {
    extern __shared__ char sdata[];
    const uint32_t sb = smem_u32(sdata);
    const int tid = threadIdx.x;
    const int wid = tid >> 5, lid = tid & 31;
    const int row0 = blockIdx.x * TILE_M;

    // A loader: 2 threads/row; thread covers one 64-elem sub-tile of the 128-k super-chunk
    const int rA = tid >> 1;            // 0..127
    const int sub_a = tid & 1;          // which sub-tile this thread fills
    // B loader (cp.async): 4 threads/row
    const int rB = tid >> 2;            // 0..63
    const int qB = tid & 3;             // 32B quarter of the 128B row

    // ldmatrix lane maps
    const int idx = lid >> 3;
    const int a_row = wid * 16 + (idx & 1) * 8 + (lid & 7);
    const uint32_t a_rowbyte = (uint32_t)a_row * 128;
    const uint32_t a_xor = (uint32_t)(a_row & 7) << 4;
    const uint32_t a_k2 = (uint32_t)(idx >> 1) * 16;
    const int b_n0 = (idx >> 1) * 8 + (lid & 7);
    const uint32_t b_k2 = (uint32_t)(idx & 1) * 16;
    uint32_t b_rowbyte[4], b_xor[4];
#pragma unroll
    for (int j = 0; j < 4; j++) {
        int nr = j * 16 + b_n0;
        b_rowbyte[j] = (uint32_t)nr * 128;
        b_xor[j] = (uint32_t)(nr & 7) << 4;
    }

    float acc[8][4] = {};
    float4 a_raw[16];

    const float* xrow = x + (size_t)(row0 + rA) * H + sub_a * 64;
    const size_t wrow = (size_t)rB * H;

    // ---- prologue: load super-chunk 0 into buf0 ----
    {
        const uint32_t bufu = sb;
#pragma unroll
        for (int s = 0; s < 2; s++)
#pragma unroll
            for (int p = 0; p < 2; p++) {
                const __nv_bfloat16* src = (p ? g_Wl : g_Wh) + wrow + s * 64 + qB * 16;
                uint32_t dbase = bufu + s * SUB_SZ + B_OFFS + p * B_SZ;
                CP_ASYNC16(dbase + sw128((uint32_t)(rB * 128 + qB * 32)), src);
                CP_ASYNC16(dbase + sw128((uint32_t)(rB * 128 + qB * 32 + 16)), src + 8);
            }
        CP_COMMIT();
#pragma unroll
        for (int j = 0; j < 16; j++) a_raw[j] = ((const float4*)xrow)[j];
        char* abuf = sdata + sub_a * SUB_SZ;
#pragma unroll
        for (int j = 0; j < 8; j++) {
            float v[8] = {a_raw[2 * j].x, a_raw[2 * j].y, a_raw[2 * j].z, a_raw[2 * j].w,
                          a_raw[2 * j + 1].x, a_raw[2 * j + 1].y, a_raw[2 * j + 1].z, a_raw[2 * j + 1].w};
            uint32_t ph[4], pl[4];
#pragma unroll
            for (int q = 0; q < 4; q++) {
                float h0, l0, h1, l1;
                split2(v[2 * q], h0, l0);
                split2(v[2 * q + 1], h1, l1);
                ph[q] = packbf(h0, h1); pl[q] = packbf(l0, l1);
            }
            uint32_t off = sw128((uint32_t)(rA * 128 + j * 16));
            *(uint4*)(abuf + off)        = make_uint4(ph[0], ph[1], ph[2], ph[3]);
            *(uint4*)(abuf + A_SZ + off) = make_uint4(pl[0], pl[1], pl[2], pl[3]);
        }
        CP_WAIT0();
        __syncthreads();
    }

    for (int c = 0; c < NSUPER; c++) {
        const uint32_t sbuf = sb + (uint32_t)((c & 1) * BUF_SZ);
        const int nb = (c + 1) & 1;
        const bool more = (c + 1 < NSUPER);

        // ---- prefetch super-chunk c+1: B via cp.async, A via LDG ----
        if (more) {
            const uint32_t bufu = sb + (uint32_t)(nb * BUF_SZ);
            const size_t k0 = (size_t)(c + 1) * SUPERK;
#pragma unroll
            for (int s = 0; s < 2; s++)
#pragma unroll
                for (int p = 0; p < 2; p++) {
                    const __nv_bfloat16* src = (p ? g_Wl : g_Wh) + wrow + k0 + s * 64 + qB * 16;
                    uint32_t dbase = bufu + s * SUB_SZ + B_OFFS + p * B_SZ;
                    CP_ASYNC16(dbase + sw128((uint32_t)(rB * 128 + qB * 32)), src);
                    CP_ASYNC16(dbase + sw128((uint32_t)(rB * 128 + qB * 32 + 16)), src + 8);
                }
            CP_COMMIT();
#pragma unroll
            for (int j = 0; j < 16; j++) a_raw[j] = ((const float4*)(xrow + k0))[j];
        }

        // ---- MMA over both sub-tiles ----
#pragma unroll
        for (int s = 0; s < 2; s++) {
            const uint32_t sbs = sbuf + s * SUB_SZ;
#pragma unroll
            for (int ks = 0; ks < 4; ks++) {
                const uint32_t kcol = (uint32_t)ks * 32;
                uint32_t Af[2][4], Bh[4][4], Bl[4][4];
                LDSM4(Af[0], sbs + a_rowbyte + ((kcol + a_k2) ^ a_xor));
                LDSM4(Af[1], sbs + A_SZ + a_rowbyte + ((kcol + a_k2) ^ a_xor));
#pragma unroll
                for (int j = 0; j < 4; j++)
                    LDSM4(Bh[j], sbs + B_OFFS + b_rowbyte[j] + ((kcol + b_k2) ^ b_xor[j]));
#pragma unroll
                for (int j = 0; j < 4; j++) {
                    MMA16816(acc[2 * j],     Af[0], Bh[j][0], Bh[j][1]);
                    MMA16816(acc[2 * j + 1], Af[0], Bh[j][2], Bh[j][3]);
                }
#pragma unroll
                for (int j = 0; j < 4; j++)
                    LDSM4(Bl[j], sbs + B_OFFS + B_SZ + b_rowbyte[j] + ((kcol + b_k2) ^ b_xor[j]));
#pragma unroll
                for (int j = 0; j < 4; j++) {
                    MMA16816(acc[2 * j],     Af[1], Bh[j][0], Bh[j][1]);
                    MMA16816(acc[2 * j + 1], Af[1], Bh[j][2], Bh[j][3]);
                }
#pragma unroll
                for (int j = 0; j < 4; j++) {
                    MMA16816(acc[2 * j],     Af[0], Bl[j][0], Bl[j][1]);
                    MMA16816(acc[2 * j + 1], Af[0], Bl[j][2], Bl[j][3]);
                }
            }
        }

        // ---- split & store prefetched A ----
        if (more) {
            char* abuf = sdata + nb * BUF_SZ + sub_a * SUB_SZ;
#pragma unroll
            for (int j = 0; j < 8; j++) {
                float v[8] = {a_raw[2 * j].x, a_raw[2 * j].y, a_raw[2 * j].z, a_raw[2 * j].w,
                              a_raw[2 * j + 1].x, a_raw[2 * j + 1].y, a_raw[2 * j + 1].z, a_raw[2 * j + 1].w};
                uint32_t ph[4], pl[4];
#pragma unroll
                for (int q = 0; q < 4; q++) {
                    float h0, l0, h1, l1;
                    split2(v[2 * q], h0, l0);
                    split2(v[2 * q + 1], h1, l1);
                    ph[q] = packbf(h0, h1); pl[q] = packbf(l0, l1);
                }
                uint32_t off = sw128((uint32_t)(rA * 128 + j * 16));
                *(uint4*)(abuf + off)        = make_uint4(ph[0], ph[1], ph[2], ph[3]);
                *(uint4*)(abuf + A_SZ + off) = make_uint4(pl[0], pl[1], pl[2], pl[3]);
            }
            CP_WAIT0();
            __syncthreads();
        }
    }

    // ---- C frags -> smem logits (overlay buf0; last MMA read buf1) ----
    float* lg = (float*)sdata;
    {
        const int r0f = wid * 16 + (lid >> 2);
        const int c0f = (lid & 3) * 2;
#pragma unroll
        for (int nt = 0; nt < 8; nt++) {
            int col = nt * 8 + c0f;
            lg[r0f * 65 + col]           = acc[nt][0];
            lg[r0f * 65 + col + 1]       = acc[nt][1];
            lg[(r0f + 8) * 65 + col]     = acc[nt][2];
            lg[(r0f + 8) * 65 + col + 1] = acc[nt][3];
        }
    }
    __syncthreads();

    // ---- per-token softmax / top-2 / near-tie flag / reductions ----
    float* s_part = (float*)(sdata + OFF_SP);  // [4][64]
    if (tid < 128) {
        float p[E];
#pragma unroll
        for (int e = 0; e < E; e++) p[e] = lg[tid * 65 + e];

        float mx = p[0];
#pragma unroll
        for (int e = 1; e < E; e++) mx = fmaxf(mx, p[e]);
        float denom = 0.f;
#pragma unroll
        for (int e = 0; e < E; e++) { p[e] = __expf(p[e] - mx); denom += p[e]; }
        const float inv = 1.f / denom;
#pragma unroll
        for (int e = 0; e < E; e++) p[e] *= inv;

        float m1 = -1.f, m2 = -1.f, m3 = -1.f;
        int i1 = 0, i2 = 0;
#pragma unroll
        for (int e = 0; e < E; e++) {
            float v = p[e];
            if (v > m1)      { m3 = m2; m2 = m1; i2 = i1; m1 = v; i1 = e; }
            else if (v > m2) { m3 = m2; m2 = v; i2 = e; }
            else if (v > m3) { m3 = v; }
        }
        const int token = row0 + tid;
        const float d = m1 + m2 + 1e-6f;
        out[(size_t)token * 2 + 0] = m1 / d;
        out[(size_t)token * 2 + 1] = m2 / d;
        float* oidx = out + (size_t)2 * N;
        oidx[(size_t)token * 2 + 0] = (float)i1;
        oidx[(size_t)token * 2 + 1] = (float)i2;

        atomicAdd(&g_cnt[i1], 1);
        atomicAdd(&g_cnt[i2], 1);

        if ((m1 - m2 < 6e-5f * m1) || (m2 - m3 < 6e-5f * m2)) {
            int s = atomicAdd(&g_nflag, 1);
            if (s < MAXFLAG) g_flaglist[s] = token;
        }

#pragma unroll
        for (int e = 0; e < E; e++) {
            float v = p[e];
            v += __shfl_xor_sync(0xffffffffu, v, 16);
            v += __shfl_xor_sync(0xffffffffu, v, 8);
            v += __shfl_xor_sync(0xffffffffu, v, 4);
            v += __shfl_xor_sync(0xffffffffu, v, 2);
            v += __shfl_xor_sync(0xffffffffu, v, 1);
            if (lid == 0) s_part[wid * E + e] = v;
        }
    }
    __syncthreads();
    if (tid < E) {
        float s = s_part[tid] + s_part[E + tid] + s_part[2 * E + tid] + s_part[3 * E + tid];
        g_partial[blockIdx.x * E + tid] = s;
    }
}

// ---------------- kernel 2: exact fp32 fixup (1 block per flagged token) ----------------
__global__ __launch_bounds__(256) void fixup_kernel(const float* __restrict__ x,
                                                    const float* __restrict__ W,
                                                    float* __restrict__ out, int N) {
    int n = g_nflag;
    if (n > MAXFLAG) n = MAXFLAG;
    if (blockIdx.x >= n) return;
    const int token = g_flaglist[blockIdx.x];

    __shared__ float sq[4][E];
    __shared__ float sl[E];
    const int e = threadIdx.x & 63;
    const int q = threadIdx.x >> 6;

    const float* xr = x + (size_t)token * H + q * (H / 4);
    const float* wr = W + (size_t)e * H + q * (H / 4);
    float a = 0.f;
#pragma unroll 4
    for (int h = 0; h < H / 4; h += 4) {
        float4 xv = *(const float4*)(xr + h);
        float4 wv = *(const float4*)(wr + h);
        a += xv.x * wv.x + xv.y * wv.y + xv.z * wv.z + xv.w * wv.w;
    }
    sq[q][e] = a;
    __syncthreads();
    if (threadIdx.x < E) sl[threadIdx.x] = sq[0][threadIdx.x] + sq[1][threadIdx.x]
                                         + sq[2][threadIdx.x] + sq[3][threadIdx.x];
    __syncthreads();
    if (threadIdx.x == 0) {
        float mx = sl[0];
        for (int i = 1; i < E; i++) mx = fmaxf(mx, sl[i]);
        float Z = 0.f;
        for (int i = 0; i < E; i++) Z += __expf(sl[i] - mx);
        float m1 = -1e30f, m2 = -1e30f;
        int i1 = 0, i2 = 0;
        for (int i = 0; i < E; i++) {
            float v = sl[i];
            if (v > m1)      { m2 = m1; i2 = i1; m1 = v; i1 = i; }
            else if (v > m2) { m2 = v; i2 = i; }
        }
        float p1 = __expf(m1 - mx) / Z;
        float p2 = __expf(m2 - mx) / Z;
        float d = p1 + p2 + 1e-6f;
        float* oidx = out + (size_t)2 * N;
        int o1 = (int)oidx[(size_t)token * 2 + 0];
        int o2 = (int)oidx[(size_t)token * 2 + 1];
        out[(size_t)token * 2 + 0] = p1 / d;
        out[(size_t)token * 2 + 1] = p2 / d;
        oidx[(size_t)token * 2 + 0] = (float)i1;
        oidx[(size_t)token * 2 + 1] = (float)i2;
        atomicAdd(&g_cnt[o1], -1);
        atomicAdd(&g_cnt[o2], -1);
        atomicAdd(&g_cnt[i1], 1);
        atomicAdd(&g_cnt[i2], 1);
    }
}

// ---------------- kernel 3: aux loss + counts ----------------
__global__ __launch_bounds__(512) void finalize_kernel(float* __restrict__ out, int N) {
    __shared__ float red[8][E];
    __shared__ float s2[2];
    const int e = threadIdx.x & 63;
    const int part = threadIdx.x >> 6;
    const int nb = N / TILE_M;
    float s = 0.f;
    for (int bb = part; bb < nb; bb += 8) s += g_partial[bb * E + e];
    red[part][e] = s;
    __syncthreads();
    float val = 0.f;
    if (threadIdx.x < E) {
        s = 0.f;
#pragma unroll
        for (int r = 0; r < 8; r++) s += red[r][e];
        const float pm  = s / (float)N;
        const float cnt = (float)g_cnt[e];
        const float am  = cnt / (float)N;
        out[(size_t)4 * N + 1 + e] = cnt;
        val = pm * pm + am * am;
    }
    val += __shfl_xor_sync(0xffffffffu, val, 16);
    val += __shfl_xor_sync(0xffffffffu, val, 8);
    val += __shfl_xor_sync(0xffffffffu, val, 4);
    val += __shfl_xor_sync(0xffffffffu, val, 2);
    val += __shfl_xor_sync(0xffffffffu, val, 1);
    if ((threadIdx.x & 31) == 0 && threadIdx.x < 64) s2[threadIdx.x >> 5] = val;
    __syncthreads();
    if (threadIdx.x == 0) out[(size_t)4 * N] = (float)E * (s2[0] + s2[1]);
}

extern "C" void kernel_launch(void* const* d_in, const int* in_sizes, int n_in,
                              void* d_out, int out_size) {
    const float* x = (const float*)d_in[0];
    const float* W = (const float*)d_in[1];
    float* out = (float*)d_out;
    const int N = in_sizes[0] / H;

    cudaFuncSetAttribute(gemm_kernel, cudaFuncAttributeMaxDynamicSharedMemorySize,
                         SMEM_TOTAL);

    prep_kernel<<<(E * H + 255) / 256, 256>>>(W);
    gemm_kernel<<<N / TILE_M, 256, SMEM_TOTAL>>>(x, out, N);
    fixup_kernel<<<MAXFLAG, 256>>>(x, W, out, N);
    finalize_kernel<<<1, 512>>>(out, N);
}

// round 13
// speedup vs baseline: 1.0055x; 1.0055x over previous
#include <cuda_runtime.h>
#include <cuda_bf16.h>
#include <cstdint>

#define H 2048
#define E 64
#define MAXN 16384
#define TILE_M 64
#define KC 64
#define CHUNKS (H / KC)  // 32
#define MAXFLAG 512

// ---------------- device scratch ----------------
__device__ __align__(16) __nv_bfloat16 g_Wh[E * H];
__device__ __align__(16) __nv_bfloat16 g_Wl[E * H];
__device__ float g_partial[(MAXN / TILE_M) * E];
__device__ int   g_cnt[E];
__device__ int   g_nflag;
__device__ int   g_flaglist[MAXFLAG];

// ---------------- helpers ----------------
__device__ __forceinline__ uint32_t smem_u32(const void* p) {
    uint32_t a;
    asm("{ .reg .u64 t; cvta.to.shared.u64 t, %1; cvt.u32.u64 %0, t; }" : "=r"(a) : "l"(p));
    return a;
}
__device__ __forceinline__ uint32_t sw128(uint32_t o) { return o ^ ((o >> 3) & 0x70); }

__device__ __forceinline__ void split2(float v, float& h, float& l) {
    h = __bfloat162float(__float2bfloat16_rn(v));
    l = v - h;
}
__device__ __forceinline__ uint32_t packbf(float a, float b) {
    __nv_bfloat162 t = __floats2bfloat162_rn(a, b);
    return *reinterpret_cast<uint32_t*>(&t);
}

#define CP_ASYNC16(dst, src)                                                             \
    asm volatile("cp.async.cg.shared.global [%0], [%1], 16;" :: "r"(dst), "l"(src))
#define CP_COMMIT()  asm volatile("cp.async.commit_group;" ::: "memory")
#define CP_WAIT0()   asm volatile("cp.async.wait_group 0;" ::: "memory")

#define LDSM4(r, addr)                                                                   \
    asm volatile("ldmatrix.sync.aligned.m8n8.x4.shared.b16 {%0,%1,%2,%3}, [%4];"         \
        : "=r"((r)[0]), "=r"((r)[1]), "=r"((r)[2]), "=r"((r)[3]) : "r"(addr))

#define MMA16816(ac, a, b0, b1)                                                          \
    asm volatile("mma.sync.aligned.m16n8k16.row.col.f32.bf16.bf16.f32 "                  \
        "{%0,%1,%2,%3}, {%4,%5,%6,%7}, {%8,%9}, {%0,%1,%2,%3};"                          \
        : "+f"((ac)[0]), "+f"((ac)[1]), "+f"((ac)[2]), "+f"((ac)[3])                     \
        : "r"((a)[0]), "r"((a)[1]), "r"((a)[2]), "r"((a)[3]), "r"(b0), "r"(b1))

// ---------------- kernel 0: split W once, zero counters ----------------
__global__ __launch_bounds__(256) void prep_kernel(const float* __restrict__ W) {
    int i = blockIdx.x * 256 + threadIdx.x;
    if (i < E * H) {
        float v = W[i], h, l;
        split2(v, h, l);
        g_Wh[i] = __float2bfloat16_rn(h);
        g_Wl[i] = __float2bfloat16_rn(l);
    }
    if (blockIdx.x == 0 && threadIdx.x < E) g_cnt[threadIdx.x] = 0;
    if (blockIdx.x == 0 && threadIdx.x == 0) g_nflag = 0;
}

// ---------------- kernel 1: fused 3-term split-bf16 HMMA GEMM, TILE_M=64, occ 2 ----------------
// Buffer (KC=64): A_hi@0 (8KB) A_lo@8K B_hi@16K B_lo@24K = 32KB; double-buffered 64KB.
static constexpr int A_SZ  = 8192;
static constexpr int B_SZ  = 8192;
static constexpr int B_OFF = 2 * A_SZ;           // 16384
static constexpr int BUF_SZ = B_OFF + 2 * B_SZ;  // 32768
static constexpr int OFF_SP = 2 * BUF_SZ;        // 65536
static constexpr int SMEM_TOTAL = OFF_SP + 2 * E * 4;  // 66048

__global__ __launch_bounds__(128, 2) void gemm_kernel(const float* __restrict__ x,
                                                      float* __restrict__ out, int N) {
    extern __shared__ char sdata[];
    const uint32_t sb = smem_u32(sdata);
    const int tid = threadIdx.x;
    const int wid = tid >> 5, lid = tid & 31;
    const int row0 = blockIdx.x * TILE_M;

    // loaders (128 threads)
    const int rA = tid >> 1;            // 0..63
    const int kA = (tid & 1) * 32;      // k half (elements)
    const int rB = tid >> 1;            // 0..63
    const int hB = (tid & 1) * 64;      // byte half of 128B row

    // ldmatrix lane maps (4 warps, 16 rows each)
    const int idx = lid >> 3;
    const int a_row = wid * 16 + (idx & 1) * 8 + (lid & 7);
    const uint32_t a_rowbyte = (uint32_t)a_row * 128;
    const uint32_t a_xor = (uint32_t)(a_row & 7) << 4;
    const uint32_t a_k2 = (uint32_t)(idx >> 1) * 16;
    const int b_n0 = (idx >> 1) * 8 + (lid & 7);
    const uint32_t b_k2 = (uint32_t)(idx & 1) * 16;
    uint32_t b_rowbyte[4], b_xor[4];
#pragma unroll
    for (int j = 0; j < 4; j++) {
        int nr = j * 16 + b_n0;
        b_rowbyte[j] = (uint32_t)nr * 128;
        b_xor[j] = (uint32_t)(nr & 7) << 4;
    }

    float acc[8][4] = {};
    float4 a_raw[8];

    const float* xrow = x + (size_t)(row0 + rA) * H + kA;
    const size_t wrow = (size_t)rB * H;

    // ---- prologue: fill buf0 for chunk 0 ----
    {
#pragma unroll
        for (int p = 0; p < 2; p++) {
            const __nv_bfloat16* src = (p ? g_Wl : g_Wh) + wrow + hB / 2;
            uint32_t dbase = sb + B_OFF + p * B_SZ;
#pragma unroll
            for (int q = 0; q < 4; q++)
                CP_ASYNC16(dbase + sw128((uint32_t)(rB * 128 + hB + q * 16)), src + q * 8);
        }
        CP_COMMIT();
#pragma unroll
        for (int j = 0; j < 8; j++) a_raw[j] = ((const float4*)xrow)[j];
#pragma unroll
        for (int j = 0; j < 4; j++) {
            float v[8] = {a_raw[2 * j].x, a_raw[2 * j].y, a_raw[2 * j].z, a_raw[2 * j].w,
                          a_raw[2 * j + 1].x, a_raw[2 * j + 1].y, a_raw[2 * j + 1].z, a_raw[2 * j + 1].w};
            uint32_t ph[4], pl[4];
#pragma unroll
            for (int q = 0; q < 4; q++) {
                float h0, l0, h1, l1;
                split2(v[2 * q], h0, l0);
                split2(v[2 * q + 1], h1, l1);
                ph[q] = packbf(h0, h1); pl[q] = packbf(l0, l1);
            }
            uint32_t off = sw128((uint32_t)(rA * 128 + kA * 2 + j * 16));
            *(uint4*)(sdata + off)        = make_uint4(ph[0], ph[1], ph[2], ph[3]);
            *(uint4*)(sdata + A_SZ + off) = make_uint4(pl[0], pl[1], pl[2], pl[3]);
        }
        CP_WAIT0();
        __syncthreads();
    }

    for (int c = 0; c < CHUNKS; c++) {
        const uint32_t sbuf = sb + (uint32_t)((c & 1) * BUF_SZ);
        const int nb = (c + 1) & 1;
        const bool more = (c + 1 < CHUNKS);

        // ---- prefetch chunk c+1 ----
        if (more) {
            const size_t k0 = (size_t)(c + 1) * KC;
#pragma unroll
            for (int p = 0; p < 2; p++) {
                const __nv_bfloat16* src = (p ? g_Wl : g_Wh) + wrow + k0 + hB / 2;
                uint32_t dbase = sb + nb * BUF_SZ + B_OFF + p * B_SZ;
#pragma unroll
                for (int q = 0; q < 4; q++)
                    CP_ASYNC16(dbase + sw128((uint32_t)(rB * 128 + hB + q * 16)), src + q * 8);
            }
            CP_COMMIT();
#pragma unroll
            for (int j = 0; j < 8; j++) a_raw[j] = ((const float4*)(xrow + k0))[j];
        }

        // ---- MMA: 3 term-pairs, reuse-distance-8 ----
#pragma unroll
        for (int ks = 0; ks < 4; ks++) {
            const uint32_t kcol = (uint32_t)ks * 32;
            uint32_t Af[2][4], Bh[4][4], Bl[4][4];
            LDSM4(Af[0], sbuf + a_rowbyte + ((kcol + a_k2) ^ a_xor));
            LDSM4(Af[1], sbuf + A_SZ + a_rowbyte + ((kcol + a_k2) ^ a_xor));
#pragma unroll
            for (int j = 0; j < 4; j++)
                LDSM4(Bh[j], sbuf + B_OFF + b_rowbyte[j] + ((kcol + b_k2) ^ b_xor[j]));
#pragma unroll
            for (int j = 0; j < 4; j++) {
                MMA16816(acc[2 * j],     Af[0], Bh[j][0], Bh[j][1]);
                MMA16816(acc[2 * j + 1], Af[0], Bh[j][2], Bh[j][3]);
            }
#pragma unroll
            for (int j = 0; j < 4; j++)
                LDSM4(Bl[j], sbuf + B_OFF + B_SZ + b_rowbyte[j] + ((kcol + b_k2) ^ b_xor[j]));
#pragma unroll
            for (int j = 0; j < 4; j++) {
                MMA16816(acc[2 * j],     Af[1], Bh[j][0], Bh[j][1]);
                MMA16816(acc[2 * j + 1], Af[1], Bh[j][2], Bh[j][3]);
            }
#pragma unroll
            for (int j = 0; j < 4; j++) {
                MMA16816(acc[2 * j],     Af[0], Bl[j][0], Bl[j][1]);
                MMA16816(acc[2 * j + 1], Af[0], Bl[j][2], Bl[j][3]);
            }
        }

        // ---- split & store prefetched A ----
        if (more) {
            char* abuf = sdata + nb * BUF_SZ;
#pragma unroll
            for (int j = 0; j < 4; j++) {
                float v[8] = {a_raw[2 * j].x, a_raw[2 * j].y, a_raw[2 * j].z, a_raw[2 * j].w,
                              a_raw[2 * j + 1].x, a_raw[2 * j + 1].y, a_raw[2 * j + 1].z, a_raw[2 * j + 1].w};
                uint32_t ph[4], pl[4];
#pragma unroll
                for (int q = 0; q < 4; q++) {
                    float h0, l0, h1, l1;
                    split2(v[2 * q], h0, l0);
                    split2(v[2 * q + 1], h1, l1);
                    ph[q] = packbf(h0, h1); pl[q] = packbf(l0, l1);
                }
                uint32_t off = sw128((uint32_t)(rA * 128 + kA * 2 + j * 16));
                *(uint4*)(abuf + off)        = make_uint4(ph[0], ph[1], ph[2], ph[3]);
                *(uint4*)(abuf + A_SZ + off) = make_uint4(pl[0], pl[1], pl[2], pl[3]);
            }
            CP_WAIT0();
            __syncthreads();
        }
    }

    // ---- C frags -> smem logits (overlay buf0; last MMA read buf1) ----
    float* lg = (float*)sdata;
    {
        const int r0f = wid * 16 + (lid >> 2);
        const int c0f = (lid & 3) * 2;
#pragma unroll
        for (int nt = 0; nt < 8; nt++) {
            int col = nt * 8 + c0f;
            lg[r0f * 65 + col]           = acc[nt][0];
            lg[r0f * 65 + col + 1]       = acc[nt][1];
            lg[(r0f + 8) * 65 + col]     = acc[nt][2];
            lg[(r0f + 8) * 65 + col + 1] = acc[nt][3];
        }
    }
    __syncthreads();

    // ---- per-token softmax / top-2 / near-tie flag / reductions (threads 0..63) ----
    float* s_part = (float*)(sdata + OFF_SP);  // [2][64]
    if (tid < 64) {
        float p[E];
#pragma unroll
        for (int e = 0; e < E; e++) p[e] = lg[tid * 65 + e];

        float mx = p[0];
#pragma unroll
        for (int e = 1; e < E; e++) mx = fmaxf(mx, p[e]);
        float denom = 0.f;
#pragma unroll
        for (int e = 0; e < E; e++) { p[e] = __expf(p[e] - mx); denom += p[e]; }
        const float inv = 1.f / denom;
#pragma unroll
        for (int e = 0; e < E; e++) p[e] *= inv;

        float m1 = -1.f, m2 = -1.f, m3 = -1.f;
        int i1 = 0, i2 = 0;
#pragma unroll
        for (int e = 0; e < E; e++) {
            float v = p[e];
            if (v > m1)      { m3 = m2; m2 = m1; i2 = i1; m1 = v; i1 = e; }
            else if (v > m2) { m3 = m2; m2 = v; i2 = e; }
            else if (v > m3) { m3 = v; }
        }
        const int token = row0 + tid;
        const float d = m1 + m2 + 1e-6f;
        out[(size_t)token * 2 + 0] = m1 / d;
        out[(size_t)token * 2 + 1] = m2 / d;
        float* oidx = out + (size_t)2 * N;
        oidx[(size_t)token * 2 + 0] = (float)i1;
        oidx[(size_t)token * 2 + 1] = (float)i2;

        atomicAdd(&g_cnt[i1], 1);
        atomicAdd(&g_cnt[i2], 1);

        if ((m1 - m2 < 6e-5f * m1) || (m2 - m3 < 6e-5f * m2)) {
            int s = atomicAdd(&g_nflag, 1);
            if (s < MAXFLAG) g_flaglist[s] = token;
        }

#pragma unroll
        for (int e = 0; e < E; e++) {
            float v = p[e];
            v += __shfl_xor_sync(0xffffffffu, v, 16);
            v += __shfl_xor_sync(0xffffffffu, v, 8);
            v += __shfl_xor_sync(0xffffffffu, v, 4);
            v += __shfl_xor_sync(0xffffffffu, v, 2);
            v += __shfl_xor_sync(0xffffffffu, v, 1);
            if (lid == 0) s_part[wid * E + e] = v;
        }
    }
    __syncthreads();
    if (tid < E) {
        g_partial[blockIdx.x * E + tid] = s_part[tid] + s_part[E + tid];
    }
}

// ---------------- kernel 2: exact fp32 fixup (1 block per flagged token) ----------------
__global__ __launch_bounds__(256) void fixup_kernel(const float* __restrict__ x,
                                                    const float* __restrict__ W,
                                                    float* __restrict__ out, int N) {
    int n = g_nflag;
    if (n > MAXFLAG) n = MAXFLAG;
    if (blockIdx.x >= n) return;
    const int token = g_flaglist[blockIdx.x];

    __shared__ float sq[4][E];
    __shared__ float sl[E];
    const int e = threadIdx.x & 63;
    const int q = threadIdx.x >> 6;

    const float* xr = x + (size_t)token * H + q * (H / 4);
    const float* wr = W + (size_t)e * H + q * (H / 4);
    float a = 0.f;
#pragma unroll 4
    for (int h = 0; h < H / 4; h += 4) {
        float4 xv = *(const float4*)(xr + h);
        float4 wv = *(const float4*)(wr + h);
        a += xv.x * wv.x + xv.y * wv.y + xv.z * wv.z + xv.w * wv.w;
    }
    sq[q][e] = a;
    __syncthreads();
    if (threadIdx.x < E) sl[threadIdx.x] = sq[0][threadIdx.x] + sq[1][threadIdx.x]
                                         + sq[2][threadIdx.x] + sq[3][threadIdx.x];
    __syncthreads();
    if (threadIdx.x == 0) {
        float mx = sl[0];
        for (int i = 1; i < E; i++) mx = fmaxf(mx, sl[i]);
        float Z = 0.f;
        for (int i = 0; i < E; i++) Z += __expf(sl[i] - mx);
        float m1 = -1e30f, m2 = -1e30f;
        int i1 = 0, i2 = 0;
        for (int i = 0; i < E; i++) {
            float v = sl[i];
            if (v > m1)      { m2 = m1; i2 = i1; m1 = v; i1 = i; }
            else if (v > m2) { m2 = v; i2 = i; }
        }
        float p1 = __expf(m1 - mx) / Z;
        float p2 = __expf(m2 - mx) / Z;
        float d = p1 + p2 + 1e-6f;
        float* oidx = out + (size_t)2 * N;
        int o1 = (int)oidx[(size_t)token * 2 + 0];
        int o2 = (int)oidx[(size_t)token * 2 + 1];
        out[(size_t)token * 2 + 0] = p1 / d;
        out[(size_t)token * 2 + 1] = p2 / d;
        oidx[(size_t)token * 2 + 0] = (float)i1;
        oidx[(size_t)token * 2 + 1] = (float)i2;
        atomicAdd(&g_cnt[o1], -1);
        atomicAdd(&g_cnt[o2], -1);
        atomicAdd(&g_cnt[i1], 1);
        atomicAdd(&g_cnt[i2], 1);
    }
}

// ---------------- kernel 3: aux loss + counts ----------------
__global__ __launch_bounds__(512) void finalize_kernel(float* __restrict__ out, int N) {
    __shared__ float red[8][E];
    __shared__ float s2[2];
    const int e = threadIdx.x & 63;
    const int part = threadIdx.x >> 6;
    const int nb = N / TILE_M;
    float s = 0.f;
    for (int bb = part; bb < nb; bb += 8) s += g_partial[bb * E + e];
    red[part][e] = s;
    __syncthreads();
    float val = 0.f;
    if (threadIdx.x < E) {
        s = 0.f;
#pragma unroll
        for (int r = 0; r < 8; r++) s += red[r][e];
        const float pm  = s / (float)N;
        const float cnt = (float)g_cnt[e];
        const float am  = cnt / (float)N;
        out[(size_t)4 * N + 1 + e] = cnt;
        val = pm * pm + am * am;
    }
    val += __shfl_xor_sync(0xffffffffu, val, 16);
    val += __shfl_xor_sync(0xffffffffu, val, 8);
    val += __shfl_xor_sync(0xffffffffu, val, 4);
    val += __shfl_xor_sync(0xffffffffu, val, 2);
    val += __shfl_xor_sync(0xffffffffu, val, 1);
    if ((threadIdx.x & 31) == 0 && threadIdx.x < 64) s2[threadIdx.x >> 5] = val;
    __syncthreads();
    if (threadIdx.x == 0) out[(size_t)4 * N] = (float)E * (s2[0] + s2[1]);
}

extern "C" void kernel_launch(void* const* d_in, const int* in_sizes, int n_in,
                              void* d_out, int out_size) {
    const float* x = (const float*)d_in[0];
    const float* W = (const float*)d_in[1];
    float* out = (float*)d_out;
    const int N = in_sizes[0] / H;

    cudaFuncSetAttribute(gemm_kernel, cudaFuncAttributeMaxDynamicSharedMemorySize,
                         SMEM_TOTAL);

    prep_kernel<<<(E * H + 255) / 256, 256>>>(W);
    gemm_kernel<<<N / TILE_M, 128, SMEM_TOTAL>>>(x, out, N);
    fixup_kernel<<<MAXFLAG, 256>>>(x, W, out, N);
    finalize_kernel<<<1, 512>>>(out, N);
}

// round 14
// speedup vs baseline: 1.0993x; 1.0934x over previous
#include <cuda_runtime.h>
#include <cuda_bf16.h>
#include <cstdint>

#define H 2048
#define E 64
#define MAXN 16384
#define NX (MAXN * H)
#define TILE_M 128
#define KC 64
#define CHUNKS (H / KC)  // 32
#define STAGES 4
#define MAXFLAG 512

// ---------------- device scratch ----------------
__device__ __align__(16) __nv_bfloat16 g_Xh[NX];
__device__ __align__(16) __nv_bfloat16 g_Xl[NX];
__device__ __align__(16) __nv_bfloat16 g_Wh[E * H];
__device__ __align__(16) __nv_bfloat16 g_Wl[E * H];
__device__ float g_partial[(MAXN / TILE_M) * E];
__device__ int   g_cnt[E];
__device__ int   g_nflag;
__device__ int   g_flaglist[MAXFLAG];

// ---------------- helpers ----------------
__device__ __forceinline__ uint32_t smem_u32(const void* p) {
    uint32_t a;
    asm("{ .reg .u64 t; cvta.to.shared.u64 t, %1; cvt.u32.u64 %0, t; }" : "=r"(a) : "l"(p));
    return a;
}
__device__ __forceinline__ uint32_t sw128(uint32_t o) { return o ^ ((o >> 3) & 0x70); }

__device__ __forceinline__ void split2(float v, float& h, float& l) {
    h = __bfloat162float(__float2bfloat16_rn(v));
    l = v - h;
}
__device__ __forceinline__ uint32_t packbf(float a, float b) {
    __nv_bfloat162 t = __floats2bfloat162_rn(a, b);
    return *reinterpret_cast<uint32_t*>(&t);
}

#define CP_ASYNC16(dst, src)                                                             \
    asm volatile("cp.async.cg.shared.global [%0], [%1], 16;" :: "r"(dst), "l"(src))
#define CP_COMMIT()  asm volatile("cp.async.commit_group;" ::: "memory")
#define CP_WAIT2()   asm volatile("cp.async.wait_group 2;" ::: "memory")
#define CP_WAIT0()   asm volatile("cp.async.wait_group 0;" ::: "memory")

#define LDSM4(r, addr)                                                                   \
    asm volatile("ldmatrix.sync.aligned.m8n8.x4.shared.b16 {%0,%1,%2,%3}, [%4];"         \
        : "=r"((r)[0]), "=r"((r)[1]), "=r"((r)[2]), "=r"((r)[3]) : "r"(addr))

#define MMA16816(ac, a, b0, b1)                                                          \
    asm volatile("mma.sync.aligned.m16n8k16.row.col.f32.bf16.bf16.f32 "                  \
        "{%0,%1,%2,%3}, {%4,%5,%6,%7}, {%8,%9}, {%0,%1,%2,%3};"                          \
        : "+f"((ac)[0]), "+f"((ac)[1]), "+f"((ac)[2]), "+f"((ac)[3])                     \
        : "r"((a)[0]), "r"((a)[1]), "r"((a)[2]), "r"((a)[3]), "r"(b0), "r"(b1))

// ---------------- kernel 0: split x AND W once, zero counters ----------------
// Grid: NX/2048 blocks for x, then E*H/2048 blocks for W.
__global__ __launch_bounds__(256) void prep_kernel(const float* __restrict__ x,
                                                   const float* __restrict__ W) {
    const size_t i0 = ((size_t)blockIdx.x * 256 + threadIdx.x) * 8;
    const float* src;
    __nv_bfloat16 *dh, *dl;
    size_t i;
    if (i0 < (size_t)NX) {
        src = x; dh = g_Xh; dl = g_Xl; i = i0;
    } else {
        i = i0 - (size_t)NX;
        if (i >= (size_t)(E * H)) return;
        src = W; dh = g_Wh; dl = g_Wl;
        if (blockIdx.x == (unsigned)(NX / 2048) && threadIdx.x < 65) {
            if (threadIdx.x < 64) g_cnt[threadIdx.x] = 0;
            else g_nflag = 0;
        }
    }
    float4 v0 = *(const float4*)(src + i);
    float4 v1 = *(const float4*)(src + i + 4);
    float vv[8] = {v0.x, v0.y, v0.z, v0.w, v1.x, v1.y, v1.z, v1.w};
    uint32_t ph[4], pl[4];
#pragma unroll
    for (int q = 0; q < 4; q++) {
        float h0, l0, h1, l1;
        split2(vv[2 * q], h0, l0);
        split2(vv[2 * q + 1], h1, l1);
        ph[q] = packbf(h0, h1);
        pl[q] = packbf(l0, l1);
    }
    *(uint4*)(dh + i) = make_uint4(ph[0], ph[1], ph[2], ph[3]);
    *(uint4*)(dl + i) = make_uint4(pl[0], pl[1], pl[2], pl[3]);
}

// ---------------- kernel 1: pure cp.async + LDSM + HMMA GEMM (3-term) ----------------
// Per stage: A_hi@0 (16KB) A_lo@16K B_hi@32K B_lo@40K = 48KB; 4 stages = 192KB.
static constexpr int A_SZ   = 16384;
static constexpr int B_SZ   = 8192;
static constexpr int B_OFFS = 2 * A_SZ;             // 32768
static constexpr int STG_SZ = B_OFFS + 2 * B_SZ;    // 49152
static constexpr int OFF_SP = STAGES * STG_SZ;      // 196608
static constexpr int SMEM_TOTAL = OFF_SP + 4 * E * 4;  // 197632

__global__ __launch_bounds__(256, 1) void gemm_kernel(float* __restrict__ out, int N) {
    extern __shared__ char sdata[];
    const uint32_t sb = smem_u32(sdata);
    const int tid = threadIdx.x;
    const int wid = tid >> 5, lid = tid & 31;
    const int row0 = blockIdx.x * TILE_M;

    // ldmatrix lane maps (8 warps, 16 rows each)
    const int idx = lid >> 3;
    const int a_row = wid * 16 + (idx & 1) * 8 + (lid & 7);
    const uint32_t a_rowbyte = (uint32_t)a_row * 128;
    const uint32_t a_xor = (uint32_t)(a_row & 7) << 4;
    const uint32_t a_k2 = (uint32_t)(idx >> 1) * 16;
    const int b_n0 = (idx >> 1) * 8 + (lid & 7);
    const uint32_t b_k2 = (uint32_t)(idx & 1) * 16;
    uint32_t b_rowbyte[4], b_xor[4];
#pragma unroll
    for (int j = 0; j < 4; j++) {
        int nr = j * 16 + b_n0;
        b_rowbyte[j] = (uint32_t)nr * 128;
        b_xor[j] = (uint32_t)(nr & 7) << 4;
    }

    // cp.async loader maps: A 1024 16B-units (4/thread), B 512 units (2/thread)
    // unit u: row = u>>3, col = u&7; dst sw128(row*128+col*16); src row*H + k0 + col*8
    float acc[8][4] = {};

    // ---- prologue: stages 0..2 ----
#pragma unroll
    for (int s = 0; s < STAGES - 1; s++) {
        const uint32_t stg = sb + s * STG_SZ;
        const int k0 = s * KC;
#pragma unroll
        for (int q = 0; q < 4; q++) {
            const int u = q * 256 + tid;
            const int r = u >> 3, cc = u & 7;
            const uint32_t dst = sw128((uint32_t)(r * 128 + cc * 16));
            const size_t srcoff = (size_t)(row0 + r) * H + k0 + cc * 8;
            CP_ASYNC16(stg + dst, g_Xh + srcoff);
            CP_ASYNC16(stg + A_SZ + dst, g_Xl + srcoff);
        }
#pragma unroll
        for (int q = 0; q < 2; q++) {
            const int u = q * 256 + tid;
            const int r = u >> 3, cc = u & 7;
            const uint32_t dst = sw128((uint32_t)(r * 128 + cc * 16));
            const size_t srcoff = (size_t)r * H + k0 + cc * 8;
            CP_ASYNC16(stg + B_OFFS + dst, g_Wh + srcoff);
            CP_ASYNC16(stg + B_OFFS + B_SZ + dst, g_Wl + srcoff);
        }
        CP_COMMIT();
    }

    for (int c = 0; c < CHUNKS; c++) {
        CP_WAIT2();        // stage c's group retired (<=2 younger pending)
        __syncthreads();   // all threads done with stage (c-1) MMA + see stage c data

        // ---- issue stage c+3 ----
        if (c + STAGES - 1 < CHUNKS) {
            const uint32_t stg = sb + ((c + STAGES - 1) & (STAGES - 1)) * STG_SZ;
            const int k0 = (c + STAGES - 1) * KC;
#pragma unroll
            for (int q = 0; q < 4; q++) {
                const int u = q * 256 + tid;
                const int r = u >> 3, cc = u & 7;
                const uint32_t dst = sw128((uint32_t)(r * 128 + cc * 16));
                const size_t srcoff = (size_t)(row0 + r) * H + k0 + cc * 8;
                CP_ASYNC16(stg + dst, g_Xh + srcoff);
                CP_ASYNC16(stg + A_SZ + dst, g_Xl + srcoff);
            }
#pragma unroll
            for (int q = 0; q < 2; q++) {
                const int u = q * 256 + tid;
                const int r = u >> 3, cc = u & 7;
                const uint32_t dst = sw128((uint32_t)(r * 128 + cc * 16));
                const size_t srcoff = (size_t)r * H + k0 + cc * 8;
                CP_ASYNC16(stg + B_OFFS + dst, g_Wh + srcoff);
                CP_ASYNC16(stg + B_OFFS + B_SZ + dst, g_Wl + srcoff);
            }
        }
        CP_COMMIT();  // always commit (possibly empty) to keep group count uniform

        // ---- MMA on stage c: 3 term-pairs, reuse-distance-8 ----
        const uint32_t sbuf = sb + (c & (STAGES - 1)) * STG_SZ;
#pragma unroll
        for (int ks = 0; ks < 4; ks++) {
            const uint32_t kcol = (uint32_t)ks * 32;
            uint32_t Af[2][4], Bh[4][4], Bl[4][4];
            LDSM4(Af[0], sbuf + a_rowbyte + ((kcol + a_k2) ^ a_xor));
            LDSM4(Af[1], sbuf + A_SZ + a_rowbyte + ((kcol + a_k2) ^ a_xor));
#pragma unroll
            for (int j = 0; j < 4; j++)
                LDSM4(Bh[j], sbuf + B_OFFS + b_rowbyte[j] + ((kcol + b_k2) ^ b_xor[j]));
#pragma unroll
            for (int j = 0; j < 4; j++) {
                MMA16816(acc[2 * j],     Af[0], Bh[j][0], Bh[j][1]);
                MMA16816(acc[2 * j + 1], Af[0], Bh[j][2], Bh[j][3]);
            }
#pragma unroll
            for (int j = 0; j < 4; j++)
                LDSM4(Bl[j], sbuf + B_OFFS + B_SZ + b_rowbyte[j] + ((kcol + b_k2) ^ b_xor[j]));
#pragma unroll
            for (int j = 0; j < 4; j++) {
                MMA16816(acc[2 * j],     Af[1], Bh[j][0], Bh[j][1]);
                MMA16816(acc[2 * j + 1], Af[1], Bh[j][2], Bh[j][3]);
            }
#pragma unroll
            for (int j = 0; j < 4; j++) {
                MMA16816(acc[2 * j],     Af[0], Bl[j][0], Bl[j][1]);
                MMA16816(acc[2 * j + 1], Af[0], Bl[j][2], Bl[j][3]);
            }
        }
    }

    CP_WAIT0();
    __syncthreads();

    // ---- C frags -> smem logits (overlay stage 0; stride 65 floats) ----
    float* lg = (float*)sdata;
    {
        const int r0f = wid * 16 + (lid >> 2);
        const int c0f = (lid & 3) * 2;
#pragma unroll
        for (int nt = 0; nt < 8; nt++) {
            int col = nt * 8 + c0f;
            lg[r0f * 65 + col]           = acc[nt][0];
            lg[r0f * 65 + col + 1]       = acc[nt][1];
            lg[(r0f + 8) * 65 + col]     = acc[nt][2];
            lg[(r0f + 8) * 65 + col + 1] = acc[nt][3];
        }
    }
    __syncthreads();

    // ---- per-token softmax / top-2 / near-tie flag / reductions ----
    float* s_part = (float*)(sdata + OFF_SP);  // [4][64]
    if (tid < 128) {
        float p[E];
#pragma unroll
        for (int e = 0; e < E; e++) p[e] = lg[tid * 65 + e];

        float mx = p[0];
#pragma unroll
        for (int e = 1; e < E; e++) mx = fmaxf(mx, p[e]);
        float denom = 0.f;
#pragma unroll
        for (int e = 0; e < E; e++) { p[e] = __expf(p[e] - mx); denom += p[e]; }
        const float inv = 1.f / denom;
#pragma unroll
        for (int e = 0; e < E; e++) p[e] *= inv;

        float m1 = -1.f, m2 = -1.f, m3 = -1.f;
        int i1 = 0, i2 = 0;
#pragma unroll
        for (int e = 0; e < E; e++) {
            float v = p[e];
            if (v > m1)      { m3 = m2; m2 = m1; i2 = i1; m1 = v; i1 = e; }
            else if (v > m2) { m3 = m2; m2 = v; i2 = e; }
            else if (v > m3) { m3 = v; }
        }
        const int token = row0 + tid;
        const float d = m1 + m2 + 1e-6f;
        out[(size_t)token * 2 + 0] = m1 / d;
        out[(size_t)token * 2 + 1] = m2 / d;
        float* oidx = out + (size_t)2 * N;
        oidx[(size_t)token * 2 + 0] = (float)i1;
        oidx[(size_t)token * 2 + 1] = (float)i2;

        atomicAdd(&g_cnt[i1], 1);
        atomicAdd(&g_cnt[i2], 1);

        if ((m1 - m2 < 6e-5f * m1) || (m2 - m3 < 6e-5f * m2)) {
            int s = atomicAdd(&g_nflag, 1);
            if (s < MAXFLAG) g_flaglist[s] = token;
        }

#pragma unroll
        for (int e = 0; e < E; e++) {
            float v = p[e];
            v += __shfl_xor_sync(0xffffffffu, v, 16);
            v += __shfl_xor_sync(0xffffffffu, v, 8);
            v += __shfl_xor_sync(0xffffffffu, v, 4);
            v += __shfl_xor_sync(0xffffffffu, v, 2);
            v += __shfl_xor_sync(0xffffffffu, v, 1);
            if (lid == 0) s_part[wid * E + e] = v;
        }
    }
    __syncthreads();
    if (tid < E) {
        float s = s_part[tid] + s_part[E + tid] + s_part[2 * E + tid] + s_part[3 * E + tid];
        g_partial[blockIdx.x * E + tid] = s;
    }
}

// ---------------- kernel 2: exact fp32 fixup (1 block per flagged token) ----------------
__global__ __launch_bounds__(256) void fixup_kernel(const float* __restrict__ x,
                                                    const float* __restrict__ W,
                                                    float* __restrict__ out, int N) {
    int n = g_nflag;
    if (n > MAXFLAG) n = MAXFLAG;
    if (blockIdx.x >= n) return;
    const int token = g_flaglist[blockIdx.x];

    __shared__ float sq[4][E];
    __shared__ float sl[E];
    const int e = threadIdx.x & 63;
    const int q = threadIdx.x >> 6;

    const float* xr = x + (size_t)token * H + q * (H / 4);
    const float* wr = W + (size_t)e * H + q * (H / 4);
    float a = 0.f;
#pragma unroll 4
    for (int h = 0; h < H / 4; h += 4) {
        float4 xv = *(const float4*)(xr + h);
        float4 wv = *(const float4*)(wr + h);
        a += xv.x * wv.x + xv.y * wv.y + xv.z * wv.z + xv.w * wv.w;
    }
    sq[q][e] = a;
    __syncthreads();
    if (threadIdx.x < E) sl[threadIdx.x] = sq[0][threadIdx.x] + sq[1][threadIdx.x]
                                         + sq[2][threadIdx.x] + sq[3][threadIdx.x];
    __syncthreads();
    if (threadIdx.x == 0) {
        float mx = sl[0];
        for (int i = 1; i < E; i++) mx = fmaxf(mx, sl[i]);
        float Z = 0.f;
        for (int i = 0; i < E; i++) Z += __expf(sl[i] - mx);
        float m1 = -1e30f, m2 = -1e30f;
        int i1 = 0, i2 = 0;
        for (int i = 0; i < E; i++) {
            float v = sl[i];
            if (v > m1)      { m2 = m1; i2 = i1; m1 = v; i1 = i; }
            else if (v > m2) { m2 = v; i2 = i; }
        }
        float p1 = __expf(m1 - mx) / Z;
        float p2 = __expf(m2 - mx) / Z;
        float d = p1 + p2 + 1e-6f;
        float* oidx = out + (size_t)2 * N;
        int o1 = (int)oidx[(size_t)token * 2 + 0];
        int o2 = (int)oidx[(size_t)token * 2 + 1];
        out[(size_t)token * 2 + 0] = p1 / d;
        out[(size_t)token * 2 + 1] = p2 / d;
        oidx[(size_t)token * 2 + 0] = (float)i1;
        oidx[(size_t)token * 2 + 1] = (float)i2;
        atomicAdd(&g_cnt[o1], -1);
        atomicAdd(&g_cnt[o2], -1);
        atomicAdd(&g_cnt[i1], 1);
        atomicAdd(&g_cnt[i2], 1);
    }
}

// ---------------- kernel 3: aux loss + counts ----------------
__global__ __launch_bounds__(512) void finalize_kernel(float* __restrict__ out, int N) {
    __shared__ float red[8][E];
    __shared__ float s2[2];
    const int e = threadIdx.x & 63;
    const int part = threadIdx.x >> 6;
    const int nb = N / TILE_M;
    float s = 0.f;
    for (int bb = part; bb < nb; bb += 8) s += g_partial[bb * E + e];
    red[part][e] = s;
    __syncthreads();
    float val = 0.f;
    if (threadIdx.x < E) {
        s = 0.f;
#pragma unroll
        for (int r = 0; r < 8; r++) s += red[r][e];
        const float pm  = s / (float)N;
        const float cnt = (float)g_cnt[e];
        const float am  = cnt / (float)N;
        out[(size_t)4 * N + 1 + e] = cnt;
        val = pm * pm + am * am;
    }
    val += __shfl_xor_sync(0xffffffffu, val, 16);
    val += __shfl_xor_sync(0xffffffffu, val, 8);
    val += __shfl_xor_sync(0xffffffffu, val, 4);
    val += __shfl_xor_sync(0xffffffffu, val, 2);
    val += __shfl_xor_sync(0xffffffffu, val, 1);
    if ((threadIdx.x & 31) == 0 && threadIdx.x < 64) s2[threadIdx.x >> 5] = val;
    __syncthreads();
    if (threadIdx.x == 0) out[(size_t)4 * N] = (float)E * (s2[0] + s2[1]);
}

extern "C" void kernel_launch(void* const* d_in, const int* in_sizes, int n_in,
                              void* d_out, int out_size) {
    const float* x = (const float*)d_in[0];
    const float* W = (const float*)d_in[1];
    float* out = (float*)d_out;
    const int N = in_sizes[0] / H;  // 16384

    cudaFuncSetAttribute(gemm_kernel, cudaFuncAttributeMaxDynamicSharedMemorySize,
                         SMEM_TOTAL);

    const int prep_blocks = NX / 2048 + (E * H) / 2048;  // 16384 + 64
    prep_kernel<<<prep_blocks, 256>>>(x, W);
    gemm_kernel<<<N / TILE_M, 256, SMEM_TOTAL>>>(out, N);
    fixup_kernel<<<MAXFLAG, 256>>>(x, W, out, N);
    finalize_kernel<<<1, 512>>>(out, N);
}